// round 10
// baseline (speedup 1.0000x reference)
#include <cuda_runtime.h>
#include <cuda_fp16.h>
#include <cstdint>

// AxialAttention: 512 independent attention problems of [S=512, c=64].
// B' = outer*8 + W; q/k/v/out element (B', s, c) at outer*262144 + s*512 + W*64 + c.
// attn output [B',512,512] contiguous, placed after `out` in d_out.
// R10: pre-convert K/V to fp16 in gmem scratch (kernel 1), then R6 structure with
// cp.async fp16 chunk staging (double-buffered), ldmatrix frags, vectorized softmax.

#define QSTRH 72           // Q smem row stride (halves)
#define BSTRH 72           // K/V chunk smem row stride (halves)
#define SSTR 516           // scores smem row stride (floats)
#define QROWS 32
#define QS_F 0
#define B0_F 1152          // Qs = 32*72 halves = 1152 floats
#define B1_F 3456          // + 64*72/2
#define SC_F 5760          // + 64*72/2
#define SMEM_FLOATS (SC_F + QROWS*SSTR)
#define NELEM 16777216     // elements in each of k, v

__device__ __half Kh_g[NELEM];
__device__ __half Vh_g[NELEM];

__device__ __forceinline__ uint32_t packh2(float a, float b) {
    __half2 h = __floats2half2_rn(a, b);
    return *reinterpret_cast<uint32_t*>(&h);
}

__device__ __forceinline__ void mma16(float* c,
        uint32_t a0, uint32_t a1, uint32_t a2, uint32_t a3,
        uint32_t b0, uint32_t b1) {
    asm volatile(
        "mma.sync.aligned.m16n8k16.row.col.f32.f16.f16.f32 "
        "{%0,%1,%2,%3},{%4,%5,%6,%7},{%8,%9},{%0,%1,%2,%3};\n"
        : "+f"(c[0]), "+f"(c[1]), "+f"(c[2]), "+f"(c[3])
        : "r"(a0), "r"(a1), "r"(a2), "r"(a3), "r"(b0), "r"(b1));
}

__device__ __forceinline__ void ldsm4(uint32_t& r0, uint32_t& r1,
                                      uint32_t& r2, uint32_t& r3, uint32_t a) {
    asm volatile("ldmatrix.sync.aligned.m8n8.x4.shared.b16 {%0,%1,%2,%3}, [%4];\n"
        : "=r"(r0), "=r"(r1), "=r"(r2), "=r"(r3) : "r"(a));
}

__device__ __forceinline__ void ldsm4t(uint32_t& r0, uint32_t& r1,
                                       uint32_t& r2, uint32_t& r3, uint32_t a) {
    asm volatile("ldmatrix.sync.aligned.m8n8.x4.trans.shared.b16 {%0,%1,%2,%3}, [%4];\n"
        : "=r"(r0), "=r"(r1), "=r"(r2), "=r"(r3) : "r"(a));
}

__device__ __forceinline__ void cp16h(__half* s, const __half* g) {
    uint32_t sa = (uint32_t)__cvta_generic_to_shared(s);
    asm volatile("cp.async.cg.shared.global [%0], [%1], 16;\n" :: "r"(sa), "l"(g));
}
#define CP_COMMIT asm volatile("cp.async.commit_group;\n" ::: "memory")
#define CP_WAIT0  asm volatile("cp.async.wait_group 0;\n" ::: "memory")

// stage a 64-row x 64-half chunk (fp16 gmem -> smem) via cp.async
__device__ __forceinline__ void load_chunk_h(__half* dst, const __half* g,
                                             int row0, int tid) {
    #pragma unroll
    for (int i = 0; i < 2; i++) {
        int e  = tid + 256 * i;      // 512 x 16B = 8KB
        int r  = e >> 3;
        int c8 = (e & 7) << 3;
        cp16h(dst + r * BSTRH + c8, g + (long)(row0 + r) * 512 + c8);
    }
}

// ---------------- kernel 1: fp32 -> fp16 conversion of K and V ----------------
__global__ __launch_bounds__(256)
void cvt_kv_kernel(const float* __restrict__ k, const float* __restrict__ v) {
    int i = blockIdx.x * blockDim.x + threadIdx.x;   // float4 index, n/4 total
    float4 a = ((const float4*)k)[i];
    float4 b = ((const float4*)v)[i];
    ((uint2*)Kh_g)[i] = make_uint2(packh2(a.x, a.y), packh2(a.z, a.w));
    ((uint2*)Vh_g)[i] = make_uint2(packh2(b.x, b.y), packh2(b.z, b.w));
}

// ---------------- kernel 2: attention ----------------
__global__ __launch_bounds__(256, 2)
void axial_attn_kernel(const float* __restrict__ q,
                       const int*   __restrict__ amask,
                       const float* __restrict__ hmask,
                       float* __restrict__ outp,
                       float* __restrict__ attnp)
{
    extern __shared__ float sm[];
    __half* Qs  = (__half*)(sm + QS_F);     // 32 x 72 halves
    __half* Bh0 = (__half*)(sm + B0_F);     // 64 x 72 halves
    __half* Bh1 = (__half*)(sm + B1_F);     // 64 x 72 halves
    float*  Sc  = sm + SC_F;                // 32 x 516 scores / P overlay

    const int tid  = threadIdx.x;
    const int w    = tid >> 5;
    const int lane = tid & 31;
    const int gid  = lane >> 2;
    const int tig  = lane & 3;
    const int rg   = w >> 2;       // row group (0/1) -> 16 rows
    const int cg   = w & 3;        // col group (0..3) -> 16 cols within chunk
    const int m0   = rg * 16;

    __half* bufs[2] = { Bh0, Bh1 };

    // ldmatrix lane addressing (within a chunk buffer)
    const uint32_t b0A = (uint32_t)__cvta_generic_to_shared(Bh0);
    const uint32_t b1A = (uint32_t)__cvta_generic_to_shared(Bh1);
    const uint32_t k_off = (uint32_t)((cg * 16 + ((lane >> 3) & 1) * 8 + (lane & 7)) * BSTRH
                                      + ((lane >> 4) & 1) * 8) * 2;
    const uint32_t v_off = (uint32_t)((((lane >> 3) & 1) * 8 + (lane & 7)) * BSTRH
                                      + cg * 16 + ((lane >> 4) & 1) * 8) * 2;
    const uint32_t kaddr[2] = { b0A + k_off, b1A + k_off };
    const uint32_t vaddr[2] = { b0A + v_off, b1A + v_off };

    const int Bp    = blockIdx.y;
    const int q0    = blockIdx.x * QROWS;
    const int outer = Bp >> 3;
    const int Wd    = Bp & 7;
    const long base = (long)outer * 262144 + (long)Wd * 64;

    const float*  qb = q + base;
    const __half* kb = Kh_g + base;
    const __half* vb = Vh_g + base;
    float* ob = outp + base;
    float* ab = attnp + (long)Bp * 262144;

    // prologue: K chunk 0 in flight
    load_chunk_h(Bh0, kb, 0, tid);
    CP_COMMIT;

    // stage Q tile (scale by 0.125, convert half)
    #pragma unroll
    for (int i = 0; i < 2; i++) {
        int idx = tid + 256 * i;
        int r   = idx >> 4;
        int c4  = (idx & 15) << 2;
        float4 t = *(const float4*)(qb + (long)(q0 + r) * 512 + c4);
        *(uint2*)(Qs + r * QSTRH + c4) =
            make_uint2(packh2(t.x * 0.125f, t.y * 0.125f),
                       packh2(t.z * 0.125f, t.w * 0.125f));
    }
    __syncthreads();

    // A fragments
    uint32_t A[4][4];
    #pragma unroll
    for (int ks = 0; ks < 4; ks++) {
        const __half* qr = Qs + (m0 + gid) * QSTRH + ks * 16 + 2 * tig;
        A[ks][0] = *(const uint32_t*)(qr);
        A[ks][1] = *(const uint32_t*)(qr + 8 * QSTRH);
        A[ks][2] = *(const uint32_t*)(qr + 8);
        A[ks][3] = *(const uint32_t*)(qr + 8 * QSTRH + 8);
    }

    // ---- QK^T over 8 chunks (double-buffered cp.async) ----
    for (int kc = 0; kc < 8; kc++) {
        CP_WAIT0;
        __syncthreads();     // cur chunk visible; prev MMA done in all warps
        if (kc < 7) load_chunk_h(bufs[(kc + 1) & 1], kb, (kc + 1) * 64, tid);
        else        load_chunk_h(bufs[0], vb, 0, tid);   // V0 hides under softmax
        CP_COMMIT;

        float C[2][4];
        #pragma unroll
        for (int nt = 0; nt < 2; nt++)
            #pragma unroll
            for (int i = 0; i < 4; i++) C[nt][i] = 0.f;

        uint32_t ka = kaddr[kc & 1];
        #pragma unroll
        for (int ks = 0; ks < 4; ks++) {
            uint32_t b0, b1, b2, b3;
            ldsm4(b0, b1, b2, b3, ka + ks * 32);
            mma16(C[0], A[ks][0], A[ks][1], A[ks][2], A[ks][3], b0, b2);
            mma16(C[1], A[ks][0], A[ks][1], A[ks][2], A[ks][3], b1, b3);
        }
        #pragma unroll
        for (int nt = 0; nt < 2; nt++) {
            int col = kc * 64 + cg * 16 + nt * 8 + tig * 2;
            float* s0 = Sc + (m0 + gid) * SSTR + col;
            *(float2*)(s0)            = make_float2(C[nt][0], C[nt][1]);
            *(float2*)(s0 + 8 * SSTR) = make_float2(C[nt][2], C[nt][3]);
        }
    }
    __syncthreads();   // all scores visible

    // ---- masked softmax + head_mask; write attn; P overlay (vectorized) ----
    for (int rr = 0; rr < 4; rr++) {
        int r    = w * 4 + rr;
        int qrow = q0 + r;
        float*     srow = Sc + r * SSTR;
        const int* mrow = amask + (long)qrow * 512;

        float sv[16];
        float mx = -INFINITY;
        #pragma unroll
        for (int j = 0; j < 4; j++) {
            int col = 4 * lane + 128 * j;
            float4 s4 = *(const float4*)(srow + col);
            int4   m4 = *(const int4*)(mrow + col);
            sv[4*j]   = (m4.x != 0) ? s4.x : -INFINITY;
            sv[4*j+1] = (m4.y != 0) ? s4.y : -INFINITY;
            sv[4*j+2] = (m4.z != 0) ? s4.z : -INFINITY;
            sv[4*j+3] = (m4.w != 0) ? s4.w : -INFINITY;
            mx = fmaxf(mx, fmaxf(fmaxf(sv[4*j], sv[4*j+1]), fmaxf(sv[4*j+2], sv[4*j+3])));
        }
        #pragma unroll
        for (int o = 16; o; o >>= 1) mx = fmaxf(mx, __shfl_xor_sync(0xFFFFFFFFu, mx, o));

        float sum = 0.f;
        #pragma unroll
        for (int j = 0; j < 16; j++) {
            float e = __expf(sv[j] - mx);
            sv[j] = e;
            sum += e;
        }
        #pragma unroll
        for (int o = 16; o; o >>= 1) sum += __shfl_xor_sync(0xFFFFFFFFu, sum, o);
        float inv = 1.0f / sum;

        const float* hrow = hmask + (long)qrow * 512;
        float*       arow = ab + (long)qrow * 512;
        __syncwarp();   // all reads of srow done before overlay writes
        #pragma unroll
        for (int j = 0; j < 4; j++) {
            int col = 4 * lane + 128 * j;
            float4 h4 = *(const float4*)(hrow + col);
            float a0 = sv[4*j]   * inv * h4.x;
            float a1 = sv[4*j+1] * inv * h4.y;
            float a2 = sv[4*j+2] * inv * h4.z;
            float a3 = sv[4*j+3] * inv * h4.w;
            float4 o4 = make_float4(a0, a1, a2, a3);
            *(float4*)(arow + col) = o4;
            // P overlay: two half2 words = uint2 at half2-index (2*lane + 64*j)
            *(uint2*)((uint32_t*)srow + 2 * lane + 64 * j) =
                make_uint2(packh2(a0, a1), packh2(a2, a3));
        }
    }

    // ---- O = P @ V over 8 chunks (V0 already in flight) ----
    float O[2][4];
    #pragma unroll
    for (int nt = 0; nt < 2; nt++)
        #pragma unroll
        for (int i = 0; i < 4; i++) O[nt][i] = 0.f;

    const uint32_t* Pr0 = (const uint32_t*)(Sc + (m0 + gid) * SSTR);
    const uint32_t* Pr1 = (const uint32_t*)(Sc + (m0 + gid + 8) * SSTR);

    for (int vc = 0; vc < 8; vc++) {
        CP_WAIT0;
        __syncthreads();     // V chunk visible; overlay writes (vc=0) / prev MMA done
        if (vc < 7) load_chunk_h(bufs[(vc + 1) & 1], vb, (vc + 1) * 64, tid);
        CP_COMMIT;

        uint32_t va = vaddr[vc & 1];
        #pragma unroll
        for (int ks = 0; ks < 4; ks++) {
            int hidx = vc * 32 + ks * 8 + tig;
            uint32_t a0 = Pr0[hidx];
            uint32_t a1 = Pr1[hidx];
            uint32_t a2 = Pr0[hidx + 4];
            uint32_t a3 = Pr1[hidx + 4];
            uint32_t b0, b1, b2, b3;
            ldsm4t(b0, b1, b2, b3, va + ks * (16 * BSTRH * 2));
            mma16(O[0], a0, a1, a2, a3, b0, b1);
            mma16(O[1], a0, a1, a2, a3, b2, b3);
        }
    }

    // ---- write out tile ----
    #pragma unroll
    for (int nt = 0; nt < 2; nt++) {
        int col = cg * 16 + nt * 8 + tig * 2;
        float* o0 = ob + (long)(q0 + m0 + gid) * 512 + col;
        *(float2*)o0 = make_float2(O[nt][0], O[nt][1]);
        float* o1 = ob + (long)(q0 + m0 + gid + 8) * 512 + col;
        *(float2*)o1 = make_float2(O[nt][2], O[nt][3]);
    }
}

extern "C" void kernel_launch(void* const* d_in, const int* in_sizes, int n_in,
                              void* d_out, int out_size) {
    const float* q  = (const float*)d_in[0];
    const float* k  = (const float*)d_in[1];
    const float* v  = (const float*)d_in[2];
    const int*   am = (const int*)d_in[3];
    const float* hm = (const float*)d_in[4];

    float* out  = (float*)d_out;
    float* attn = out + (long)in_sizes[0];

    // kernel 1: convert K/V to fp16 scratch
    cvt_kv_kernel<<<NELEM / 4 / 256, 256>>>(k, v);

    // kernel 2: attention
    size_t smem = (size_t)SMEM_FLOATS * sizeof(float);
    cudaFuncSetAttribute(axial_attn_kernel,
                         cudaFuncAttributeMaxDynamicSharedMemorySize, (int)smem);
    dim3 grid(16, 512);   // x: 32-row query tiles, y: flattened batch B'
    axial_attn_kernel<<<grid, 256, smem>>>(q, am, hm, out, attn);
}

// round 11
// speedup vs baseline: 1.4853x; 1.4853x over previous
#include <cuda_runtime.h>
#include <cuda_fp16.h>
#include <cstdint>

// AxialAttention: 512 independent attention problems of [S=512, c=64].
// B' = outer*8 + W; q/k/v/out element (B', s, c) at outer*262144 + s*512 + W*64 + c.
// attn output [B',512,512] contiguous, placed after `out` in d_out.
// R11: R10 (fp16 gmem scratch + cp.async + ldmatrix + vectorized softmax) with a
// 4-stage cp.async pipeline (3 groups in flight, wait_group 2) to hide gmem latency.

#define QSTRH 72           // Q smem row stride (halves)
#define BSTRH 72           // K/V chunk smem row stride (halves)
#define SSTR 516           // scores smem row stride (floats)
#define QROWS 32
#define BUF_F 2304         // floats per 64x72-half buffer
#define QS_F 0
#define B_F  1152
#define SC_F (B_F + 4*BUF_F)              // 10368
#define SMEM_FLOATS (SC_F + QROWS*SSTR)   // 26880
#define NELEM 16777216     // elements in each of k, v

__device__ __half Kh_g[NELEM];
__device__ __half Vh_g[NELEM];

__device__ __forceinline__ uint32_t packh2(float a, float b) {
    __half2 h = __floats2half2_rn(a, b);
    return *reinterpret_cast<uint32_t*>(&h);
}

__device__ __forceinline__ void mma16(float* c,
        uint32_t a0, uint32_t a1, uint32_t a2, uint32_t a3,
        uint32_t b0, uint32_t b1) {
    asm volatile(
        "mma.sync.aligned.m16n8k16.row.col.f32.f16.f16.f32 "
        "{%0,%1,%2,%3},{%4,%5,%6,%7},{%8,%9},{%0,%1,%2,%3};\n"
        : "+f"(c[0]), "+f"(c[1]), "+f"(c[2]), "+f"(c[3])
        : "r"(a0), "r"(a1), "r"(a2), "r"(a3), "r"(b0), "r"(b1));
}

__device__ __forceinline__ void ldsm4(uint32_t& r0, uint32_t& r1,
                                      uint32_t& r2, uint32_t& r3, uint32_t a) {
    asm volatile("ldmatrix.sync.aligned.m8n8.x4.shared.b16 {%0,%1,%2,%3}, [%4];\n"
        : "=r"(r0), "=r"(r1), "=r"(r2), "=r"(r3) : "r"(a));
}

__device__ __forceinline__ void ldsm4t(uint32_t& r0, uint32_t& r1,
                                       uint32_t& r2, uint32_t& r3, uint32_t a) {
    asm volatile("ldmatrix.sync.aligned.m8n8.x4.trans.shared.b16 {%0,%1,%2,%3}, [%4];\n"
        : "=r"(r0), "=r"(r1), "=r"(r2), "=r"(r3) : "r"(a));
}

__device__ __forceinline__ void cp16h(__half* s, const __half* g) {
    uint32_t sa = (uint32_t)__cvta_generic_to_shared(s);
    asm volatile("cp.async.cg.shared.global [%0], [%1], 16;\n" :: "r"(sa), "l"(g));
}
#define CP_COMMIT asm volatile("cp.async.commit_group;\n" ::: "memory")
#define CP_WAIT2  asm volatile("cp.async.wait_group 2;\n" ::: "memory")
#define CP_WAIT1  asm volatile("cp.async.wait_group 1;\n" ::: "memory")
#define CP_WAIT0  asm volatile("cp.async.wait_group 0;\n" ::: "memory")

// stage a 64-row x 64-half chunk (fp16 gmem -> smem) via cp.async
__device__ __forceinline__ void load_chunk_h(__half* dst, const __half* g,
                                             int row0, int tid) {
    #pragma unroll
    for (int i = 0; i < 2; i++) {
        int e  = tid + 256 * i;      // 512 x 16B = 8KB
        int r  = e >> 3;
        int c8 = (e & 7) << 3;
        cp16h(dst + r * BSTRH + c8, g + (long)(row0 + r) * 512 + c8);
    }
}

// ---------------- kernel 1: fp32 -> fp16 conversion of K and V ----------------
__global__ __launch_bounds__(256)
void cvt_kv_kernel(const float* __restrict__ k, const float* __restrict__ v) {
    int i = blockIdx.x * blockDim.x + threadIdx.x;   // float4 index
    float4 a = ((const float4*)k)[i];
    float4 b = ((const float4*)v)[i];
    ((uint2*)Kh_g)[i] = make_uint2(packh2(a.x, a.y), packh2(a.z, a.w));
    ((uint2*)Vh_g)[i] = make_uint2(packh2(b.x, b.y), packh2(b.z, b.w));
}

// ---------------- kernel 2: attention ----------------
__global__ __launch_bounds__(256, 2)
void axial_attn_kernel(const float* __restrict__ q,
                       const int*   __restrict__ amask,
                       const float* __restrict__ hmask,
                       float* __restrict__ outp,
                       float* __restrict__ attnp)
{
    extern __shared__ float sm[];
    __half* Qs = (__half*)(sm + QS_F);     // 32 x 72 halves
    float*  Sc = sm + SC_F;                // 32 x 516 scores / P overlay

    const int tid  = threadIdx.x;
    const int w    = tid >> 5;
    const int lane = tid & 31;
    const int gid  = lane >> 2;
    const int tig  = lane & 3;
    const int rg   = w >> 2;       // row group (0/1) -> 16 rows
    const int cg   = w & 3;        // col group (0..3) -> 16 cols within chunk
    const int m0   = rg * 16;

    __half* bufs[4];
    uint32_t kaddr[4], vaddr[4];
    {
        const uint32_t k_off = (uint32_t)((cg * 16 + ((lane >> 3) & 1) * 8 + (lane & 7)) * BSTRH
                                          + ((lane >> 4) & 1) * 8) * 2;
        const uint32_t v_off = (uint32_t)((((lane >> 3) & 1) * 8 + (lane & 7)) * BSTRH
                                          + cg * 16 + ((lane >> 4) & 1) * 8) * 2;
        #pragma unroll
        for (int i = 0; i < 4; i++) {
            bufs[i] = (__half*)(sm + B_F + i * BUF_F);
            uint32_t ba = (uint32_t)__cvta_generic_to_shared(bufs[i]);
            kaddr[i] = ba + k_off;
            vaddr[i] = ba + v_off;
        }
    }

    const int Bp    = blockIdx.y;
    const int q0    = blockIdx.x * QROWS;
    const int outer = Bp >> 3;
    const int Wd    = Bp & 7;
    const long base = (long)outer * 262144 + (long)Wd * 64;

    const float*  qb = q + base;
    const __half* kb = Kh_g + base;
    const __half* vb = Vh_g + base;
    float* ob = outp + base;
    float* ab = attnp + (long)Bp * 262144;

    // prologue: K0, K1, K2 in flight (3 groups)
    load_chunk_h(bufs[0], kb, 0, tid);   CP_COMMIT;
    load_chunk_h(bufs[1], kb, 64, tid);  CP_COMMIT;
    load_chunk_h(bufs[2], kb, 128, tid); CP_COMMIT;

    // stage Q tile (scale by 0.125, convert half)
    #pragma unroll
    for (int i = 0; i < 2; i++) {
        int idx = tid + 256 * i;
        int r   = idx >> 4;
        int c4  = (idx & 15) << 2;
        float4 t = *(const float4*)(qb + (long)(q0 + r) * 512 + c4);
        *(uint2*)(Qs + r * QSTRH + c4) =
            make_uint2(packh2(t.x * 0.125f, t.y * 0.125f),
                       packh2(t.z * 0.125f, t.w * 0.125f));
    }
    __syncthreads();

    // A fragments
    uint32_t A[4][4];
    #pragma unroll
    for (int ks = 0; ks < 4; ks++) {
        const __half* qr = Qs + (m0 + gid) * QSTRH + ks * 16 + 2 * tig;
        A[ks][0] = *(const uint32_t*)(qr);
        A[ks][1] = *(const uint32_t*)(qr + 8 * QSTRH);
        A[ks][2] = *(const uint32_t*)(qr + 8);
        A[ks][3] = *(const uint32_t*)(qr + 8 * QSTRH + 8);
    }

    // ---- QK^T over 8 chunks (4-stage pipeline, 3 groups in flight) ----
    for (int kc = 0; kc < 8; kc++) {
        CP_WAIT2;            // oldest group (chunk kc) landed
        __syncthreads();     // all warps done with buffer being overwritten below
        if (kc < 5) load_chunk_h(bufs[(kc + 3) & 3], kb, (kc + 3) * 64, tid);
        else        load_chunk_h(bufs[(kc + 3) & 3], vb, (kc - 5) * 64, tid);  // V0..V2
        CP_COMMIT;

        float C[2][4];
        #pragma unroll
        for (int nt = 0; nt < 2; nt++)
            #pragma unroll
            for (int i = 0; i < 4; i++) C[nt][i] = 0.f;

        uint32_t ka = kaddr[kc & 3];
        #pragma unroll
        for (int ks = 0; ks < 4; ks++) {
            uint32_t b0, b1, b2, b3;
            ldsm4(b0, b1, b2, b3, ka + ks * 32);
            mma16(C[0], A[ks][0], A[ks][1], A[ks][2], A[ks][3], b0, b2);
            mma16(C[1], A[ks][0], A[ks][1], A[ks][2], A[ks][3], b1, b3);
        }
        #pragma unroll
        for (int nt = 0; nt < 2; nt++) {
            int col = kc * 64 + cg * 16 + nt * 8 + tig * 2;
            float* s0 = Sc + (m0 + gid) * SSTR + col;
            *(float2*)(s0)            = make_float2(C[nt][0], C[nt][1]);
            *(float2*)(s0 + 8 * SSTR) = make_float2(C[nt][2], C[nt][3]);
        }
    }
    __syncthreads();   // all scores visible

    // ---- masked softmax + head_mask; write attn; P overlay (vectorized) ----
    // (V0..V2 cp.async groups are completing under this phase)
    for (int rr = 0; rr < 4; rr++) {
        int r    = w * 4 + rr;
        int qrow = q0 + r;
        float*     srow = Sc + r * SSTR;
        const int* mrow = amask + (long)qrow * 512;

        float sv[16];
        float mx = -INFINITY;
        #pragma unroll
        for (int j = 0; j < 4; j++) {
            int col = 4 * lane + 128 * j;
            float4 s4 = *(const float4*)(srow + col);
            int4   m4 = *(const int4*)(mrow + col);
            sv[4*j]   = (m4.x != 0) ? s4.x : -INFINITY;
            sv[4*j+1] = (m4.y != 0) ? s4.y : -INFINITY;
            sv[4*j+2] = (m4.z != 0) ? s4.z : -INFINITY;
            sv[4*j+3] = (m4.w != 0) ? s4.w : -INFINITY;
            mx = fmaxf(mx, fmaxf(fmaxf(sv[4*j], sv[4*j+1]), fmaxf(sv[4*j+2], sv[4*j+3])));
        }
        #pragma unroll
        for (int o = 16; o; o >>= 1) mx = fmaxf(mx, __shfl_xor_sync(0xFFFFFFFFu, mx, o));

        float sum = 0.f;
        #pragma unroll
        for (int j = 0; j < 16; j++) {
            float e = __expf(sv[j] - mx);
            sv[j] = e;
            sum += e;
        }
        #pragma unroll
        for (int o = 16; o; o >>= 1) sum += __shfl_xor_sync(0xFFFFFFFFu, sum, o);
        float inv = 1.0f / sum;

        const float* hrow = hmask + (long)qrow * 512;
        float*       arow = ab + (long)qrow * 512;
        __syncwarp();   // all reads of srow done before overlay writes
        #pragma unroll
        for (int j = 0; j < 4; j++) {
            int col = 4 * lane + 128 * j;
            float4 h4 = *(const float4*)(hrow + col);
            float a0 = sv[4*j]   * inv * h4.x;
            float a1 = sv[4*j+1] * inv * h4.y;
            float a2 = sv[4*j+2] * inv * h4.z;
            float a3 = sv[4*j+3] * inv * h4.w;
            *(float4*)(arow + col) = make_float4(a0, a1, a2, a3);
            *(uint2*)((uint32_t*)srow + 2 * lane + 64 * j) =
                make_uint2(packh2(a0, a1), packh2(a2, a3));
        }
    }

    // ---- O = P @ V over 8 chunks (V0..V2 already in flight) ----
    float O[2][4];
    #pragma unroll
    for (int nt = 0; nt < 2; nt++)
        #pragma unroll
        for (int i = 0; i < 4; i++) O[nt][i] = 0.f;

    const uint32_t* Pr0 = (const uint32_t*)(Sc + (m0 + gid) * SSTR);
    const uint32_t* Pr1 = (const uint32_t*)(Sc + (m0 + gid + 8) * SSTR);

    for (int vc = 0; vc < 8; vc++) {
        if (vc < 6)      { CP_WAIT2; }
        else if (vc == 6){ CP_WAIT1; }
        else             { CP_WAIT0; }
        __syncthreads();     // V chunk visible; P overlay (vc=0) / prev MMA done
        if (vc < 5) {
            load_chunk_h(bufs[(vc + 3) & 3], vb, (vc + 3) * 64, tid);
            CP_COMMIT;
        }

        uint32_t va = vaddr[vc & 3];
        #pragma unroll
        for (int ks = 0; ks < 4; ks++) {
            int hidx = vc * 32 + ks * 8 + tig;
            uint32_t a0 = Pr0[hidx];
            uint32_t a1 = Pr1[hidx];
            uint32_t a2 = Pr0[hidx + 4];
            uint32_t a3 = Pr1[hidx + 4];
            uint32_t b0, b1, b2, b3;
            ldsm4t(b0, b1, b2, b3, va + ks * (16 * BSTRH * 2));
            mma16(O[0], a0, a1, a2, a3, b0, b1);
            mma16(O[1], a0, a1, a2, a3, b2, b3);
        }
    }

    // ---- write out tile ----
    #pragma unroll
    for (int nt = 0; nt < 2; nt++) {
        int col = cg * 16 + nt * 8 + tig * 2;
        float* o0 = ob + (long)(q0 + m0 + gid) * 512 + col;
        *(float2*)o0 = make_float2(O[nt][0], O[nt][1]);
        float* o1 = ob + (long)(q0 + m0 + gid + 8) * 512 + col;
        *(float2*)o1 = make_float2(O[nt][2], O[nt][3]);
    }
}

extern "C" void kernel_launch(void* const* d_in, const int* in_sizes, int n_in,
                              void* d_out, int out_size) {
    const float* q  = (const float*)d_in[0];
    const float* k  = (const float*)d_in[1];
    const float* v  = (const float*)d_in[2];
    const int*   am = (const int*)d_in[3];
    const float* hm = (const float*)d_in[4];

    float* out  = (float*)d_out;
    float* attn = out + (long)in_sizes[0];

    // kernel 1: convert K/V to fp16 scratch
    cvt_kv_kernel<<<NELEM / 4 / 256, 256>>>(k, v);

    // kernel 2: attention
    size_t smem = (size_t)SMEM_FLOATS * sizeof(float);
    cudaFuncSetAttribute(axial_attn_kernel,
                         cudaFuncAttributeMaxDynamicSharedMemorySize, (int)smem);
    dim3 grid(16, 512);   // x: 32-row query tiles, y: flattened batch B'
    axial_attn_kernel<<<grid, 256, smem>>>(q, am, hm, out, attn);
}

// round 12
// speedup vs baseline: 1.5177x; 1.0218x over previous
#include <cuda_runtime.h>
#include <cuda_fp16.h>
#include <cstdint>

// AxialAttention: 512 independent attention problems of [S=512, c=64].
// B' = outer*8 + W; q/k/v/out element (B', s, c) at outer*262144 + s*512 + W*64 + c.
// attn output [B',512,512] contiguous, placed after `out` in d_out.
// R12: R11 (fp16 scratch + 4-stage cp.async + ldmatrix) with (a) QK warps owning
// 32 rows x 8 keys so each K ldsm feeds 4 MMAs (K ldsm traffic halved), and
// (b) bit-packed attention mask (64KB -> 256B mask reads per CTA).

#define QSTRH 72           // Q smem row stride (halves)
#define BSTRH 72           // K/V chunk smem row stride (halves)
#define SSTR 516           // scores smem row stride (floats)
#define QROWS 32
#define BUF_F 2304         // floats per 64x72-half buffer
#define QS_F 0
#define B_F  1152
#define SC_F (B_F + 4*BUF_F)              // 10368
#define SMEM_FLOATS (SC_F + QROWS*SSTR)   // 26880
#define NELEM 16777216     // elements in each of k, v

__device__ __half Kh_g[NELEM];
__device__ __half Vh_g[NELEM];
__device__ uint32_t Mbits_g[512 * 16];    // bit-packed attention mask

__device__ __forceinline__ uint32_t packh2(float a, float b) {
    __half2 h = __floats2half2_rn(a, b);
    return *reinterpret_cast<uint32_t*>(&h);
}

__device__ __forceinline__ void mma16(float* c,
        uint32_t a0, uint32_t a1, uint32_t a2, uint32_t a3,
        uint32_t b0, uint32_t b1) {
    asm volatile(
        "mma.sync.aligned.m16n8k16.row.col.f32.f16.f16.f32 "
        "{%0,%1,%2,%3},{%4,%5,%6,%7},{%8,%9},{%0,%1,%2,%3};\n"
        : "+f"(c[0]), "+f"(c[1]), "+f"(c[2]), "+f"(c[3])
        : "r"(a0), "r"(a1), "r"(a2), "r"(a3), "r"(b0), "r"(b1));
}

__device__ __forceinline__ void ldsm4(uint32_t& r0, uint32_t& r1,
                                      uint32_t& r2, uint32_t& r3, uint32_t a) {
    asm volatile("ldmatrix.sync.aligned.m8n8.x4.shared.b16 {%0,%1,%2,%3}, [%4];\n"
        : "=r"(r0), "=r"(r1), "=r"(r2), "=r"(r3) : "r"(a));
}

__device__ __forceinline__ void ldsm4t(uint32_t& r0, uint32_t& r1,
                                       uint32_t& r2, uint32_t& r3, uint32_t a) {
    asm volatile("ldmatrix.sync.aligned.m8n8.x4.trans.shared.b16 {%0,%1,%2,%3}, [%4];\n"
        : "=r"(r0), "=r"(r1), "=r"(r2), "=r"(r3) : "r"(a));
}

__device__ __forceinline__ void cp16h(__half* s, const __half* g) {
    uint32_t sa = (uint32_t)__cvta_generic_to_shared(s);
    asm volatile("cp.async.cg.shared.global [%0], [%1], 16;\n" :: "r"(sa), "l"(g));
}
#define CP_COMMIT asm volatile("cp.async.commit_group;\n" ::: "memory")
#define CP_WAIT2  asm volatile("cp.async.wait_group 2;\n" ::: "memory")
#define CP_WAIT1  asm volatile("cp.async.wait_group 1;\n" ::: "memory")
#define CP_WAIT0  asm volatile("cp.async.wait_group 0;\n" ::: "memory")

__device__ __forceinline__ void load_chunk_h(__half* dst, const __half* g,
                                             int row0, int tid) {
    #pragma unroll
    for (int i = 0; i < 2; i++) {
        int e  = tid + 256 * i;
        int r  = e >> 3;
        int c8 = (e & 7) << 3;
        cp16h(dst + r * BSTRH + c8, g + (long)(row0 + r) * 512 + c8);
    }
}

// ---------------- kernel 1: fp32 -> fp16 conversion of K and V ----------------
__global__ __launch_bounds__(256)
void cvt_kv_kernel(const float* __restrict__ k, const float* __restrict__ v) {
    int i = blockIdx.x * blockDim.x + threadIdx.x;
    float4 a = ((const float4*)k)[i];
    float4 b = ((const float4*)v)[i];
    ((uint2*)Kh_g)[i] = make_uint2(packh2(a.x, a.y), packh2(a.z, a.w));
    ((uint2*)Vh_g)[i] = make_uint2(packh2(b.x, b.y), packh2(b.z, b.w));
}

// ---------------- kernel 1b: bit-pack attention mask ----------------
__global__ __launch_bounds__(256)
void pack_mask_kernel(const int* __restrict__ am) {
    int widx = blockIdx.x * blockDim.x + threadIdx.x;   // 0..8191
    const int4* p = (const int4*)(am + widx * 32);
    uint32_t b = 0;
    #pragma unroll
    for (int i = 0; i < 8; i++) {
        int4 m = p[i];
        if (m.x) b |= 1u << (4 * i);
        if (m.y) b |= 1u << (4 * i + 1);
        if (m.z) b |= 1u << (4 * i + 2);
        if (m.w) b |= 1u << (4 * i + 3);
    }
    Mbits_g[widx] = b;
}

// ---------------- kernel 2: attention ----------------
__global__ __launch_bounds__(256, 2)
void axial_attn_kernel(const float* __restrict__ q,
                       const float* __restrict__ hmask,
                       float* __restrict__ outp,
                       float* __restrict__ attnp)
{
    extern __shared__ float sm[];
    __half* Qs = (__half*)(sm + QS_F);     // 32 x 72 halves
    float*  Sc = sm + SC_F;                // 32 x 516 scores / P overlay

    const int tid  = threadIdx.x;
    const int w    = tid >> 5;
    const int lane = tid & 31;
    const int gid  = lane >> 2;
    const int tig  = lane & 3;
    // PV-phase mapping (unchanged from R11)
    const int rg   = w >> 2;
    const int cg   = w & 3;
    const int m0   = rg * 16;

    __half* bufs[4];
    uint32_t kaddr[4], vaddr[4];
    {
        // QK: warp w owns keys w*8..w*8+7; ldsm4 covers chan blocks 0..3
        const uint32_t k_off = (uint32_t)((w * 8 + (lane & 7)) * BSTRH
                                          + (lane >> 3) * 8) * 2;
        const uint32_t v_off = (uint32_t)((((lane >> 3) & 1) * 8 + (lane & 7)) * BSTRH
                                          + cg * 16 + ((lane >> 4) & 1) * 8) * 2;
        #pragma unroll
        for (int i = 0; i < 4; i++) {
            bufs[i] = (__half*)(sm + B_F + i * BUF_F);
            uint32_t ba = (uint32_t)__cvta_generic_to_shared(bufs[i]);
            kaddr[i] = ba + k_off;
            vaddr[i] = ba + v_off;
        }
    }

    const int Bp    = blockIdx.y;
    const int q0    = blockIdx.x * QROWS;
    const int outer = Bp >> 3;
    const int Wd    = Bp & 7;
    const long base = (long)outer * 262144 + (long)Wd * 64;

    const float*  qb = q + base;
    const __half* kb = Kh_g + base;
    const __half* vb = Vh_g + base;
    float* ob = outp + base;
    float* ab = attnp + (long)Bp * 262144;

    // prologue: K0, K1, K2 in flight
    load_chunk_h(bufs[0], kb, 0, tid);   CP_COMMIT;
    load_chunk_h(bufs[1], kb, 64, tid);  CP_COMMIT;
    load_chunk_h(bufs[2], kb, 128, tid); CP_COMMIT;

    // stage Q tile (scale by 0.125, convert half)
    #pragma unroll
    for (int i = 0; i < 2; i++) {
        int idx = tid + 256 * i;
        int r   = idx >> 4;
        int c4  = (idx & 15) << 2;
        float4 t = *(const float4*)(qb + (long)(q0 + r) * 512 + c4);
        *(uint2*)(Qs + r * QSTRH + c4) =
            make_uint2(packh2(t.x * 0.125f, t.y * 0.125f),
                       packh2(t.z * 0.125f, t.w * 0.125f));
    }
    __syncthreads();

    // A fragments: rows 0..31 (two m16 groups), k=64
    uint32_t A[2][4][4];
    #pragma unroll
    for (int g = 0; g < 2; g++)
        #pragma unroll
        for (int ks = 0; ks < 4; ks++) {
            const __half* qr = Qs + (g * 16 + gid) * QSTRH + ks * 16 + 2 * tig;
            A[g][ks][0] = *(const uint32_t*)(qr);
            A[g][ks][1] = *(const uint32_t*)(qr + 8 * QSTRH);
            A[g][ks][2] = *(const uint32_t*)(qr + 8);
            A[g][ks][3] = *(const uint32_t*)(qr + 8 * QSTRH + 8);
        }

    // ---- QK^T over 8 chunks (4-stage pipeline; warp = 32 rows x 8 keys) ----
    for (int kc = 0; kc < 8; kc++) {
        CP_WAIT2;
        __syncthreads();
        if (kc < 5) load_chunk_h(bufs[(kc + 3) & 3], kb, (kc + 3) * 64, tid);
        else        load_chunk_h(bufs[(kc + 3) & 3], vb, (kc - 5) * 64, tid);
        CP_COMMIT;

        float C[2][4];
        #pragma unroll
        for (int g = 0; g < 2; g++)
            #pragma unroll
            for (int i = 0; i < 4; i++) C[g][i] = 0.f;

        uint32_t ka = kaddr[kc & 3];
        uint32_t b0, b1, b2, b3;
        ldsm4(b0, b1, b2, b3, ka);          // chans 0-31 for this warp's 8 keys
        mma16(C[0], A[0][0][0], A[0][0][1], A[0][0][2], A[0][0][3], b0, b1);
        mma16(C[1], A[1][0][0], A[1][0][1], A[1][0][2], A[1][0][3], b0, b1);
        mma16(C[0], A[0][1][0], A[0][1][1], A[0][1][2], A[0][1][3], b2, b3);
        mma16(C[1], A[1][1][0], A[1][1][1], A[1][1][2], A[1][1][3], b2, b3);
        ldsm4(b0, b1, b2, b3, ka + 64);     // chans 32-63
        mma16(C[0], A[0][2][0], A[0][2][1], A[0][2][2], A[0][2][3], b0, b1);
        mma16(C[1], A[1][2][0], A[1][2][1], A[1][2][2], A[1][2][3], b0, b1);
        mma16(C[0], A[0][3][0], A[0][3][1], A[0][3][2], A[0][3][3], b2, b3);
        mma16(C[1], A[1][3][0], A[1][3][1], A[1][3][2], A[1][3][3], b2, b3);

        int col = kc * 64 + w * 8 + tig * 2;
        float* s0 = Sc + gid * SSTR + col;
        *(float2*)(s0)             = make_float2(C[0][0], C[0][1]);
        *(float2*)(s0 + 8 * SSTR)  = make_float2(C[0][2], C[0][3]);
        *(float2*)(s0 + 16 * SSTR) = make_float2(C[1][0], C[1][1]);
        *(float2*)(s0 + 24 * SSTR) = make_float2(C[1][2], C[1][3]);
    }
    __syncthreads();   // all scores visible

    // ---- masked softmax (bit mask) + head_mask; write attn; P overlay ----
    for (int rr = 0; rr < 4; rr++) {
        int r    = w * 4 + rr;
        int qrow = q0 + r;
        float* srow = Sc + r * SSTR;
        const uint32_t* mrowW = Mbits_g + qrow * 16;

        const int sh = (lane & 7) * 4;
        float sv[16];
        float mx = -INFINITY;
        #pragma unroll
        for (int j = 0; j < 4; j++) {
            int col = 4 * lane + 128 * j;
            float4 s4 = *(const float4*)(srow + col);
            uint32_t mw = mrowW[(lane >> 3) + 4 * j] >> sh;
            sv[4*j]   = (mw & 1u) ? s4.x : -INFINITY;
            sv[4*j+1] = (mw & 2u) ? s4.y : -INFINITY;
            sv[4*j+2] = (mw & 4u) ? s4.z : -INFINITY;
            sv[4*j+3] = (mw & 8u) ? s4.w : -INFINITY;
            mx = fmaxf(mx, fmaxf(fmaxf(sv[4*j], sv[4*j+1]), fmaxf(sv[4*j+2], sv[4*j+3])));
        }
        #pragma unroll
        for (int o = 16; o; o >>= 1) mx = fmaxf(mx, __shfl_xor_sync(0xFFFFFFFFu, mx, o));

        float sum = 0.f;
        #pragma unroll
        for (int j = 0; j < 16; j++) {
            float e = __expf(sv[j] - mx);
            sv[j] = e;
            sum += e;
        }
        #pragma unroll
        for (int o = 16; o; o >>= 1) sum += __shfl_xor_sync(0xFFFFFFFFu, sum, o);
        float inv = 1.0f / sum;

        const float* hrow = hmask + (long)qrow * 512;
        float*       arow = ab + (long)qrow * 512;
        __syncwarp();
        #pragma unroll
        for (int j = 0; j < 4; j++) {
            int col = 4 * lane + 128 * j;
            float4 h4 = *(const float4*)(hrow + col);
            float a0 = sv[4*j]   * inv * h4.x;
            float a1 = sv[4*j+1] * inv * h4.y;
            float a2 = sv[4*j+2] * inv * h4.z;
            float a3 = sv[4*j+3] * inv * h4.w;
            *(float4*)(arow + col) = make_float4(a0, a1, a2, a3);
            *(uint2*)((uint32_t*)srow + 2 * lane + 64 * j) =
                make_uint2(packh2(a0, a1), packh2(a2, a3));
        }
    }

    // ---- O = P @ V over 8 chunks (V0..V2 already in flight) ----
    float O[2][4];
    #pragma unroll
    for (int nt = 0; nt < 2; nt++)
        #pragma unroll
        for (int i = 0; i < 4; i++) O[nt][i] = 0.f;

    const uint32_t* Pr0 = (const uint32_t*)(Sc + (m0 + gid) * SSTR);
    const uint32_t* Pr1 = (const uint32_t*)(Sc + (m0 + gid + 8) * SSTR);

    for (int vc = 0; vc < 8; vc++) {
        if (vc < 6)      { CP_WAIT2; }
        else if (vc == 6){ CP_WAIT1; }
        else             { CP_WAIT0; }
        __syncthreads();
        if (vc < 5) {
            load_chunk_h(bufs[(vc + 3) & 3], vb, (vc + 3) * 64, tid);
            CP_COMMIT;
        }

        uint32_t va = vaddr[vc & 3];
        #pragma unroll
        for (int ks = 0; ks < 4; ks++) {
            int hidx = vc * 32 + ks * 8 + tig;
            uint32_t a0 = Pr0[hidx];
            uint32_t a1 = Pr1[hidx];
            uint32_t a2 = Pr0[hidx + 4];
            uint32_t a3 = Pr1[hidx + 4];
            uint32_t b0, b1, b2, b3;
            ldsm4t(b0, b1, b2, b3, va + ks * (16 * BSTRH * 2));
            mma16(O[0], a0, a1, a2, a3, b0, b1);
            mma16(O[1], a0, a1, a2, a3, b2, b3);
        }
    }

    // ---- write out tile ----
    #pragma unroll
    for (int nt = 0; nt < 2; nt++) {
        int col = cg * 16 + nt * 8 + tig * 2;
        float* o0 = ob + (long)(q0 + m0 + gid) * 512 + col;
        *(float2*)o0 = make_float2(O[nt][0], O[nt][1]);
        float* o1 = ob + (long)(q0 + m0 + gid + 8) * 512 + col;
        *(float2*)o1 = make_float2(O[nt][2], O[nt][3]);
    }
}

extern "C" void kernel_launch(void* const* d_in, const int* in_sizes, int n_in,
                              void* d_out, int out_size) {
    const float* q  = (const float*)d_in[0];
    const float* k  = (const float*)d_in[1];
    const float* v  = (const float*)d_in[2];
    const int*   am = (const int*)d_in[3];
    const float* hm = (const float*)d_in[4];

    float* out  = (float*)d_out;
    float* attn = out + (long)in_sizes[0];

    cvt_kv_kernel<<<NELEM / 4 / 256, 256>>>(k, v);
    pack_mask_kernel<<<32, 256>>>(am);

    size_t smem = (size_t)SMEM_FLOATS * sizeof(float);
    cudaFuncSetAttribute(axial_attn_kernel,
                         cudaFuncAttributeMaxDynamicSharedMemorySize, (int)smem);
    dim3 grid(16, 512);
    axial_attn_kernel<<<grid, 256, smem>>>(q, hm, out, attn);
}